// round 3
// baseline (speedup 1.0000x reference)
#include <cuda_runtime.h>
#include <cstdint>

// Problem constants (fixed shapes from reference)
#define BATCH   4
#define SLEN    2048
#define DMODEL  1024
#define NHEADS  16
#define DHEAD   64
#define MROWS   (BATCH * SLEN)   // 8192

// Scratch (allocation-free rule: __device__ globals)
__device__ float g_Q[(size_t)BATCH * NHEADS * SLEN * DHEAD];   // [b,h,s,d], pre-scaled by 1/8
__device__ float g_K[(size_t)BATCH * NHEADS * SLEN * DHEAD];   // [b,h,s,d]
__device__ float g_V[(size_t)BATCH * NHEADS * SLEN * DHEAD];   // [b,h,s,d]
__device__ float g_AO[(size_t)MROWS * DMODEL];                 // attention output [b,s, h*d]

// ---------------------------------------------------------------------------
// SGEMM (NT): C[M,N] = A[M,K] * B[N,K]^T  (both operands K-contiguous)
// 128x128 block tile, 16 K-step, 256 threads, 8x8 microtile.
// Double-buffered smem + register prefetch: one __syncthreads per K-step.
// MODE 1: QKV epilogue — RoPE on Q/K, fold 1/sqrt(dk) into Q, scatter to
//         g_Q/g_K/g_V in [b,h,s,d] layout
// MODE 2: A operand comes from g_AO (device scratch), plain store to C
// ---------------------------------------------------------------------------
constexpr int BM = 128, BN = 128, BK = 16;
constexpr int LDS_A = BM + 4;                         // pad: conflict-free transpose store
constexpr int GEMM_SMEM = 2 * 2 * BK * LDS_A * 4;     // 67584 B

template <int MODE>
__global__ __launch_bounds__(256)
void sgemm_nt(const float* __restrict__ A, const float* __restrict__ Bw,
              float* __restrict__ C, const int* __restrict__ tpos,
              int M, int N, int K)
{
    extern __shared__ __align__(16) float sm[];
    float* Asm = sm;                       // As[2][BK][LDS_A]
    float* Bsm = sm + 2 * BK * LDS_A;      // Bs[2][BK][LDS_A]

    const float* Ap = (MODE == 2) ? (const float*)g_AO : A;

    const int tid = threadIdx.x;
    const int tx = tid & 15, ty = tid >> 4;
    const int mBase = blockIdx.y * BM;
    const int nBase = blockIdx.x * BN;

    int rowL[2], cvL[2];
#pragma unroll
    for (int ld = 0; ld < 2; ld++) {
        int id = tid + ld * 256;        // 0..511
        rowL[ld] = id >> 2;             // 0..127
        cvL[ld]  = (id & 3) << 2;       // {0,4,8,12}
    }

    float acc[8][8];
#pragma unroll
    for (int i = 0; i < 8; i++)
#pragma unroll
        for (int j = 0; j < 8; j++) acc[i][j] = 0.f;

    float4 pa[2], pb[2];
#pragma unroll
    for (int ld = 0; ld < 2; ld++) {
        pa[ld] = *(const float4*)(Ap + (size_t)(mBase + rowL[ld]) * K + cvL[ld]);
        pb[ld] = *(const float4*)(Bw + (size_t)(nBase + rowL[ld]) * K + cvL[ld]);
    }
#pragma unroll
    for (int ld = 0; ld < 2; ld++) {
        float* a = Asm;
        float* b = Bsm;
        a[(cvL[ld] + 0) * LDS_A + rowL[ld]] = pa[ld].x;
        a[(cvL[ld] + 1) * LDS_A + rowL[ld]] = pa[ld].y;
        a[(cvL[ld] + 2) * LDS_A + rowL[ld]] = pa[ld].z;
        a[(cvL[ld] + 3) * LDS_A + rowL[ld]] = pa[ld].w;
        b[(cvL[ld] + 0) * LDS_A + rowL[ld]] = pb[ld].x;
        b[(cvL[ld] + 1) * LDS_A + rowL[ld]] = pb[ld].y;
        b[(cvL[ld] + 2) * LDS_A + rowL[ld]] = pb[ld].z;
        b[(cvL[ld] + 3) * LDS_A + rowL[ld]] = pb[ld].w;
    }
    __syncthreads();

    const int nT = K / BK;
    for (int t = 0; t < nT; t++) {
        if (t + 1 < nT) {
            int k0 = (t + 1) * BK;
#pragma unroll
            for (int ld = 0; ld < 2; ld++) {
                pa[ld] = *(const float4*)(Ap + (size_t)(mBase + rowL[ld]) * K + k0 + cvL[ld]);
                pb[ld] = *(const float4*)(Bw + (size_t)(nBase + rowL[ld]) * K + k0 + cvL[ld]);
            }
        }

        const float* a = Asm + (t & 1) * BK * LDS_A;
        const float* b = Bsm + (t & 1) * BK * LDS_A;
#pragma unroll
        for (int kk = 0; kk < BK; kk++) {
            float4 a0 = *(const float4*)&a[kk * LDS_A + ty * 4];
            float4 a1 = *(const float4*)&a[kk * LDS_A + 64 + ty * 4];
            float4 b0 = *(const float4*)&b[kk * LDS_A + tx * 4];
            float4 b1 = *(const float4*)&b[kk * LDS_A + 64 + tx * 4];
            float ra[8] = {a0.x, a0.y, a0.z, a0.w, a1.x, a1.y, a1.z, a1.w};
            float rb[8] = {b0.x, b0.y, b0.z, b0.w, b1.x, b1.y, b1.z, b1.w};
#pragma unroll
            for (int i = 0; i < 8; i++)
#pragma unroll
                for (int j = 0; j < 8; j++)
                    acc[i][j] = fmaf(ra[i], rb[j], acc[i][j]);
        }

        if (t + 1 < nT) {
            float* an = Asm + ((t + 1) & 1) * BK * LDS_A;
            float* bn = Bsm + ((t + 1) & 1) * BK * LDS_A;
#pragma unroll
            for (int ld = 0; ld < 2; ld++) {
                an[(cvL[ld] + 0) * LDS_A + rowL[ld]] = pa[ld].x;
                an[(cvL[ld] + 1) * LDS_A + rowL[ld]] = pa[ld].y;
                an[(cvL[ld] + 2) * LDS_A + rowL[ld]] = pa[ld].z;
                an[(cvL[ld] + 3) * LDS_A + rowL[ld]] = pa[ld].w;
                bn[(cvL[ld] + 0) * LDS_A + rowL[ld]] = pb[ld].x;
                bn[(cvL[ld] + 1) * LDS_A + rowL[ld]] = pb[ld].y;
                bn[(cvL[ld] + 2) * LDS_A + rowL[ld]] = pb[ld].z;
                bn[(cvL[ld] + 3) * LDS_A + rowL[ld]] = pb[ld].w;
            }
            __syncthreads();
        }
    }

    // Epilogue: 16 float4 stores per thread (columns 4-aligned -> RoPE pairs
    // and head/part boundaries never split a float4)
#pragma unroll
    for (int rb2 = 0; rb2 < 2; rb2++) {
#pragma unroll
        for (int i = 0; i < 4; i++) {
            int m = mBase + rb2 * 64 + ty * 4 + i;
#pragma unroll
            for (int cb = 0; cb < 2; cb++) {
                int n = nBase + cb * 64 + tx * 4;
                float4 v = make_float4(acc[rb2 * 4 + i][cb * 4 + 0],
                                       acc[rb2 * 4 + i][cb * 4 + 1],
                                       acc[rb2 * 4 + i][cb * 4 + 2],
                                       acc[rb2 * 4 + i][cb * 4 + 3]);
                if (MODE == 1) {
                    int b    = m >> 11;          // m / SLEN
                    int s    = m & (SLEN - 1);
                    int part = n >> 10;          // 0:q 1:k 2:v
                    int rem  = n & 1023;
                    int h    = rem >> 6;
                    int d    = rem & 63;
                    float* dst;
                    if (part == 2) {
                        dst = g_V;
                    } else {
                        float pos = (float)tpos[s];
                        // inv_freq = 10000^(-d/64) = exp2(-d * log2(10000)/64)
                        float a0 = pos * exp2f((float)d       * -0.20762050593f);
                        float a1 = pos * exp2f((float)(d + 2) * -0.20762050593f);
                        float s0, c0, s1, c1;
                        sincosf(a0, &s0, &c0);
                        sincosf(a1, &s1, &c1);
                        float4 r;
                        r.x = c0 * v.x - s0 * v.y;
                        r.y = s0 * v.x + c0 * v.y;
                        r.z = c1 * v.z - s1 * v.w;
                        r.w = s1 * v.z + c1 * v.w;
                        if (part == 0) {   // fold 1/sqrt(64) into Q
                            r.x *= 0.125f; r.y *= 0.125f;
                            r.z *= 0.125f; r.w *= 0.125f;
                            dst = g_Q;
                        } else {
                            dst = g_K;
                        }
                        v = r;
                    }
                    size_t idx = (((size_t)b * NHEADS + h) * SLEN + s) * DHEAD + d;
                    *(float4*)(dst + idx) = v;
                } else {
                    *(float4*)(C + (size_t)m * N + n) = v;
                }
            }
        }
    }
}

// ---------------------------------------------------------------------------
// Flash attention (causal): BM=BN=64, d=64, 256 threads, 4x4 microtile.
// grid = (SLEN/64 q-tiles, BATCH*NHEADS); q-tile index REVERSED so the
// heaviest CTAs (most kv tiles) launch first. K/V tiles are prefetched into
// registers one iteration ahead (gmem latency hidden behind tile compute).
// ---------------------------------------------------------------------------
constexpr int AT_STR  = 68;                       // smem row stride (pad)
constexpr int AT_SMEM = 4 * 64 * AT_STR * 4;      // Qt + Kt + Vs + Ps = 69632 B

__global__ __launch_bounds__(256)
void flash_attn()
{
    extern __shared__ __align__(16) float sm[];
    float* Qt = sm;                    // [d][row]  (Q^T), stride AT_STR
    float* Kt = sm + 1 * 64 * AT_STR;  // [d][col]  (K^T)
    float* Vs = sm + 2 * 64 * AT_STR;  // [j][dd]
    float* Ps = sm + 3 * 64 * AT_STR;  // [j][row]  (P^T)

    const int tid = threadIdx.x;
    const int tx = tid & 15, ty = tid >> 4;
    const int bh = blockIdx.y;
    const int qt = gridDim.x - 1 - blockIdx.x;   // reversed scheduling
    const int i0 = qt * 64;

    // Per-thread K/V load coords (4 rows of 16 thread-columns, float4 each)
    int rowKV[4], d4KV[4];
#pragma unroll
    for (int ld = 0; ld < 4; ld++) {
        int id = tid + ld * 256;     // 0..1023
        rowKV[ld] = id >> 4;         // 0..63
        d4KV[ld]  = (id & 15) << 2;  // 0,4,...,60
    }

    // Load Q tile (transposed into smem)
    const float* Qg = g_Q + ((size_t)bh * SLEN + i0) * DHEAD;
#pragma unroll
    for (int ld = 0; ld < 4; ld++) {
        float4 q = *(const float4*)(Qg + rowKV[ld] * DHEAD + d4KV[ld]);
        Qt[(d4KV[ld] + 0) * AT_STR + rowKV[ld]] = q.x;
        Qt[(d4KV[ld] + 1) * AT_STR + rowKV[ld]] = q.y;
        Qt[(d4KV[ld] + 2) * AT_STR + rowKV[ld]] = q.z;
        Qt[(d4KV[ld] + 3) * AT_STR + rowKV[ld]] = q.w;
    }

    // Prefetch KV tile 0 into registers
    const float* Kg0 = g_K + (size_t)bh * SLEN * DHEAD;
    const float* Vg0 = g_V + (size_t)bh * SLEN * DHEAD;
    float4 pk[4], pv[4];
#pragma unroll
    for (int ld = 0; ld < 4; ld++) {
        pk[ld] = *(const float4*)(Kg0 + rowKV[ld] * DHEAD + d4KV[ld]);
        pv[ld] = *(const float4*)(Vg0 + rowKV[ld] * DHEAD + d4KV[ld]);
    }

    float m_i[4], l_i[4], o[4][4];
#pragma unroll
    for (int i = 0; i < 4; i++) {
        m_i[i] = -3.0e38f;
        l_i[i] = 0.f;
#pragma unroll
        for (int c = 0; c < 4; c++) o[i][c] = 0.f;
    }

    for (int t = 0; t <= qt; t++) {
        __syncthreads();   // prior-iter readers of Kt/Vs/Ps done (noop cost iter 0)
        // Commit prefetched K/V to smem
#pragma unroll
        for (int ld = 0; ld < 4; ld++) {
            Kt[(d4KV[ld] + 0) * AT_STR + rowKV[ld]] = pk[ld].x;
            Kt[(d4KV[ld] + 1) * AT_STR + rowKV[ld]] = pk[ld].y;
            Kt[(d4KV[ld] + 2) * AT_STR + rowKV[ld]] = pk[ld].z;
            Kt[(d4KV[ld] + 3) * AT_STR + rowKV[ld]] = pk[ld].w;
            *(float4*)(Vs + rowKV[ld] * AT_STR + d4KV[ld]) = pv[ld];
        }
        __syncthreads();

        // Prefetch next KV tile (consumed next iteration)
        if (t + 1 <= qt) {
            const float* Kg = Kg0 + (size_t)(t + 1) * 64 * DHEAD;
            const float* Vg = Vg0 + (size_t)(t + 1) * 64 * DHEAD;
#pragma unroll
            for (int ld = 0; ld < 4; ld++) {
                pk[ld] = *(const float4*)(Kg + rowKV[ld] * DHEAD + d4KV[ld]);
                pv[ld] = *(const float4*)(Vg + rowKV[ld] * DHEAD + d4KV[ld]);
            }
        }

        // S = Q K^T  (Q already carries the 1/sqrt(dk) scale)
        float sc[4][4];
#pragma unroll
        for (int i = 0; i < 4; i++)
#pragma unroll
            for (int c = 0; c < 4; c++) sc[i][c] = 0.f;

#pragma unroll 8
        for (int d = 0; d < 64; d++) {
            float4 q = *(const float4*)(Qt + d * AT_STR + ty * 4);
            float4 k = *(const float4*)(Kt + d * AT_STR + tx * 4);
            float ra[4] = {q.x, q.y, q.z, q.w};
            float rb[4] = {k.x, k.y, k.z, k.w};
#pragma unroll
            for (int i = 0; i < 4; i++)
#pragma unroll
                for (int c = 0; c < 4; c++)
                    sc[i][c] = fmaf(ra[i], rb[c], sc[i][c]);
        }

        // Causal mask on the diagonal tile only (j0 == i0 there)
        if (t == qt) {
#pragma unroll
            for (int i = 0; i < 4; i++)
#pragma unroll
                for (int c = 0; c < 4; c++)
                    if (tx * 4 + c > ty * 4 + i) sc[i][c] = -1.0e30f;
        }

        // Online softmax update (row groups = 16 threads sharing ty)
#pragma unroll
        for (int i = 0; i < 4; i++) {
            float mx = fmaxf(fmaxf(sc[i][0], sc[i][1]), fmaxf(sc[i][2], sc[i][3]));
#pragma unroll
            for (int off = 8; off > 0; off >>= 1)
                mx = fmaxf(mx, __shfl_xor_sync(0xffffffffu, mx, off, 16));
            float mn = fmaxf(m_i[i], mx);
            float f  = __expf(m_i[i] - mn);
            m_i[i] = mn;
            float rs = 0.f;
#pragma unroll
            for (int c = 0; c < 4; c++) {
                sc[i][c] = __expf(sc[i][c] - mn);
                rs += sc[i][c];
            }
#pragma unroll
            for (int off = 8; off > 0; off >>= 1)
                rs += __shfl_xor_sync(0xffffffffu, rs, off, 16);
            l_i[i] = l_i[i] * f + rs;
#pragma unroll
            for (int c = 0; c < 4; c++) {
                o[i][c] *= f;
                Ps[(tx * 4 + c) * AT_STR + ty * 4 + i] = sc[i][c];
            }
        }
        __syncthreads();

        // O += P V
#pragma unroll 8
        for (int j = 0; j < 64; j++) {
            float4 p  = *(const float4*)(Ps + j * AT_STR + ty * 4);
            float4 vv = *(const float4*)(Vs + j * AT_STR + tx * 4);
            float pa[4] = {p.x, p.y, p.z, p.w};
            float vb[4] = {vv.x, vv.y, vv.z, vv.w};
#pragma unroll
            for (int i = 0; i < 4; i++)
#pragma unroll
                for (int c = 0; c < 4; c++)
                    o[i][c] = fmaf(pa[i], vb[c], o[i][c]);
        }
    }

    // Normalize and write to [b, s, h*64 + d] scratch
    const int b = bh >> 4, h = bh & 15;
#pragma unroll
    for (int i = 0; i < 4; i++) {
        float inv  = 1.f / l_i[i];
        int   srow = i0 + ty * 4 + i;
        float4 v = make_float4(o[i][0] * inv, o[i][1] * inv,
                               o[i][2] * inv, o[i][3] * inv);
        *(float4*)(g_AO + ((size_t)(b * SLEN + srow)) * DMODEL + h * DHEAD + tx * 4) = v;
    }
}

// ---------------------------------------------------------------------------
// Launch: inputs per metadata order: x, W_QKV, W_O, token_positions
// ---------------------------------------------------------------------------
extern "C" void kernel_launch(void* const* d_in, const int* in_sizes, int n_in,
                              void* d_out, int out_size)
{
    const float* x    = (const float*)d_in[0];   // [4,2048,1024]
    const float* wqkv = (const float*)d_in[1];   // [3072,1024]
    const float* wo   = (const float*)d_in[2];   // [1024,1024]
    const int*   tpos = (const int*)d_in[3];     // [2048] int32
    float* out = (float*)d_out;                  // [4,2048,1024]

    // Idempotent; execute immediately (not captured) under graph capture.
    cudaFuncSetAttribute(flash_attn,  cudaFuncAttributeMaxDynamicSharedMemorySize, AT_SMEM);
    cudaFuncSetAttribute(sgemm_nt<1>, cudaFuncAttributeMaxDynamicSharedMemorySize, GEMM_SMEM);
    cudaFuncSetAttribute(sgemm_nt<2>, cudaFuncAttributeMaxDynamicSharedMemorySize, GEMM_SMEM);

    dim3 blk(256);
    // 1) QKV projection + RoPE + scatter
    sgemm_nt<1><<<dim3(3 * DMODEL / BN, MROWS / BM), blk, GEMM_SMEM>>>(
        x, wqkv, nullptr, tpos, MROWS, 3 * DMODEL, DMODEL);
    // 2) causal flash attention
    flash_attn<<<dim3(SLEN / 64, BATCH * NHEADS), blk, AT_SMEM>>>();
    // 3) output projection
    sgemm_nt<2><<<dim3(DMODEL / BN, MROWS / BM), blk, GEMM_SMEM>>>(
        nullptr, wo, out, nullptr, MROWS, DMODEL, DMODEL);
}

// round 4
// speedup vs baseline: 1.4753x; 1.4753x over previous
#include <cuda_runtime.h>
#include <cstdint>

// Problem constants (fixed shapes from reference)
#define BATCH   4
#define SLEN    2048
#define DMODEL  1024
#define NHEADS  16
#define DHEAD   64
#define MROWS   (BATCH * SLEN)   // 8192

// Scratch (allocation-free rule: __device__ globals)
__device__ float g_Q[(size_t)BATCH * NHEADS * SLEN * DHEAD];   // [b,h,s,d], pre-scaled by 1/8
__device__ float g_K[(size_t)BATCH * NHEADS * SLEN * DHEAD];   // [b,h,s,d]
__device__ float g_V[(size_t)BATCH * NHEADS * SLEN * DHEAD];   // [b,h,s,d]
__device__ float g_AO[(size_t)MROWS * DMODEL];                 // attention output [b,s, h*d]

// ---------------------------------------------------------------------------
// TF32 tensor-core helpers
// ---------------------------------------------------------------------------
__device__ __forceinline__ float to_tf32(float x) {
    uint32_t r;
    asm("cvt.rna.tf32.f32 %0, %1;" : "=r"(r) : "f"(x));
    return __uint_as_float(r);
}

__device__ __forceinline__ void mma_tf32(float* d, const uint32_t* a, const uint32_t* b) {
    asm volatile(
        "mma.sync.aligned.m16n8k8.row.col.f32.tf32.tf32.f32 "
        "{%0,%1,%2,%3},{%4,%5,%6,%7},{%8,%9},{%0,%1,%2,%3};"
        : "+f"(d[0]), "+f"(d[1]), "+f"(d[2]), "+f"(d[3])
        : "r"(a[0]), "r"(a[1]), "r"(a[2]), "r"(a[3]), "r"(b[0]), "r"(b[1]));
}

// ---------------------------------------------------------------------------
// TF32 GEMM (NT): C[M,N] = A[M,K] * B[N,K]^T  (both operands K-contiguous)
// 128x128 block tile, BK=16, 256 threads (8 warps, 2x4 warp grid, warp tile
// 64x32). Double-buffered smem; inputs converted to tf32 at the smem store.
// MODE 1: QKV epilogue — RoPE on Q/K, fold 1/sqrt(dk) into Q, scatter to
//         g_Q/g_K/g_V in [b,h,s,d] layout
// MODE 2: A operand comes from g_AO (device scratch), plain store to C
// ---------------------------------------------------------------------------
constexpr int BM = 128, BN = 128, BK = 16;
constexpr int LDS_A = BM + 4;                         // pad (2-way worst in frag loads)
constexpr int GEMM_SMEM = 2 * 2 * BK * LDS_A * 4;     // 67584 B

template <int MODE>
__global__ __launch_bounds__(256)
void sgemm_nt(const float* __restrict__ A, const float* __restrict__ Bw,
              float* __restrict__ C, const int* __restrict__ tpos,
              int M, int N, int K)
{
    extern __shared__ __align__(16) float sm[];
    float* Asm = sm;                       // As[2][BK][LDS_A] (k-major)
    float* Bsm = sm + 2 * BK * LDS_A;      // Bs[2][BK][LDS_A] (k-major)

    const float* Ap = (MODE == 2) ? (const float*)g_AO : A;

    const int tid  = threadIdx.x;
    const int wid  = tid >> 5;
    const int lane = tid & 31;
    const int gid  = lane >> 2;            // 0..7
    const int tig  = lane & 3;             // 0..3
    const int wm   = wid & 1;              // 2 warp rows of 64
    const int wn   = wid >> 1;             // 4 warp cols of 32
    const int mBase = blockIdx.y * BM;
    const int nBase = blockIdx.x * BN;

    // Per-thread gmem load coordinates (2 vec4 loads each for A and B)
    int rowL[2], cvL[2];
#pragma unroll
    for (int ld = 0; ld < 2; ld++) {
        int id = tid + ld * 256;        // 0..511
        rowL[ld] = id >> 2;             // 0..127
        cvL[ld]  = (id & 3) << 2;       // {0,4,8,12}
    }

    float acc[4][4][4];
#pragma unroll
    for (int i = 0; i < 4; i++)
#pragma unroll
        for (int j = 0; j < 4; j++)
#pragma unroll
            for (int r = 0; r < 4; r++) acc[i][j][r] = 0.f;

    float4 pa[2], pb[2];
#pragma unroll
    for (int ld = 0; ld < 2; ld++) {
        pa[ld] = *(const float4*)(Ap + (size_t)(mBase + rowL[ld]) * K + cvL[ld]);
        pb[ld] = *(const float4*)(Bw + (size_t)(nBase + rowL[ld]) * K + cvL[ld]);
    }
#pragma unroll
    for (int ld = 0; ld < 2; ld++) {
        Asm[(cvL[ld] + 0) * LDS_A + rowL[ld]] = to_tf32(pa[ld].x);
        Asm[(cvL[ld] + 1) * LDS_A + rowL[ld]] = to_tf32(pa[ld].y);
        Asm[(cvL[ld] + 2) * LDS_A + rowL[ld]] = to_tf32(pa[ld].z);
        Asm[(cvL[ld] + 3) * LDS_A + rowL[ld]] = to_tf32(pa[ld].w);
        Bsm[(cvL[ld] + 0) * LDS_A + rowL[ld]] = to_tf32(pb[ld].x);
        Bsm[(cvL[ld] + 1) * LDS_A + rowL[ld]] = to_tf32(pb[ld].y);
        Bsm[(cvL[ld] + 2) * LDS_A + rowL[ld]] = to_tf32(pb[ld].z);
        Bsm[(cvL[ld] + 3) * LDS_A + rowL[ld]] = to_tf32(pb[ld].w);
    }
    __syncthreads();

    const int mw = wm * 64 + gid;   // fragment row base within tile
    const int nw = wn * 32 + gid;   // fragment col base within tile

    const int nT = K / BK;
    for (int t = 0; t < nT; t++) {
        if (t + 1 < nT) {
            int k0 = (t + 1) * BK;
#pragma unroll
            for (int ld = 0; ld < 2; ld++) {
                pa[ld] = *(const float4*)(Ap + (size_t)(mBase + rowL[ld]) * K + k0 + cvL[ld]);
                pb[ld] = *(const float4*)(Bw + (size_t)(nBase + rowL[ld]) * K + k0 + cvL[ld]);
            }
        }

        const float* a = Asm + (t & 1) * BK * LDS_A;
        const float* b = Bsm + (t & 1) * BK * LDS_A;
#pragma unroll
        for (int ks = 0; ks < BK; ks += 8) {
            uint32_t af[4][4], bf[4][2];
#pragma unroll
            for (int i = 0; i < 4; i++) {
                int m = mw + i * 16;
                af[i][0] = __float_as_uint(a[(ks + tig)     * LDS_A + m]);
                af[i][1] = __float_as_uint(a[(ks + tig)     * LDS_A + m + 8]);
                af[i][2] = __float_as_uint(a[(ks + tig + 4) * LDS_A + m]);
                af[i][3] = __float_as_uint(a[(ks + tig + 4) * LDS_A + m + 8]);
            }
#pragma unroll
            for (int j = 0; j < 4; j++) {
                int n = nw + j * 8;
                bf[j][0] = __float_as_uint(b[(ks + tig)     * LDS_A + n]);
                bf[j][1] = __float_as_uint(b[(ks + tig + 4) * LDS_A + n]);
            }
#pragma unroll
            for (int i = 0; i < 4; i++)
#pragma unroll
                for (int j = 0; j < 4; j++)
                    mma_tf32(acc[i][j], af[i], bf[j]);
        }

        if (t + 1 < nT) {
            float* an = Asm + ((t + 1) & 1) * BK * LDS_A;
            float* bn = Bsm + ((t + 1) & 1) * BK * LDS_A;
#pragma unroll
            for (int ld = 0; ld < 2; ld++) {
                an[(cvL[ld] + 0) * LDS_A + rowL[ld]] = to_tf32(pa[ld].x);
                an[(cvL[ld] + 1) * LDS_A + rowL[ld]] = to_tf32(pa[ld].y);
                an[(cvL[ld] + 2) * LDS_A + rowL[ld]] = to_tf32(pa[ld].z);
                an[(cvL[ld] + 3) * LDS_A + rowL[ld]] = to_tf32(pa[ld].w);
                bn[(cvL[ld] + 0) * LDS_A + rowL[ld]] = to_tf32(pb[ld].x);
                bn[(cvL[ld] + 1) * LDS_A + rowL[ld]] = to_tf32(pb[ld].y);
                bn[(cvL[ld] + 2) * LDS_A + rowL[ld]] = to_tf32(pb[ld].z);
                bn[(cvL[ld] + 3) * LDS_A + rowL[ld]] = to_tf32(pb[ld].w);
            }
            __syncthreads();
        }
    }

    // Epilogue: per (i, rr, j) this thread owns the float2 pair at
    // row m = mBase + wm*64 + i*16 + gid + rr*8,
    // col n = nBase + wn*32 + j*8 + tig*2  (n even -> valid RoPE pair)
#pragma unroll
    for (int i = 0; i < 4; i++) {
#pragma unroll
        for (int rr = 0; rr < 2; rr++) {
            int m = mBase + wm * 64 + i * 16 + gid + rr * 8;
#pragma unroll
            for (int j = 0; j < 4; j++) {
                int n = nBase + wn * 32 + j * 8 + tig * 2;
                float vx = acc[i][j][rr * 2 + 0];
                float vy = acc[i][j][rr * 2 + 1];
                if (MODE == 1) {
                    int b    = m >> 11;          // m / SLEN
                    int s    = m & (SLEN - 1);
                    int part = n >> 10;          // 0:q 1:k 2:v
                    int rem  = n & 1023;
                    int h    = rem >> 6;
                    int d    = rem & 63;         // even
                    float* dst;
                    float2 o2;
                    if (part == 2) {
                        dst = g_V;
                        o2 = make_float2(vx, vy);
                    } else {
                        float pos = (float)tpos[s];
                        // theta^(-d/64) = exp2(-d * log2(10000)/64)
                        float ang = pos * exp2f((float)d * -0.20762050593f);
                        float sn, cs;
                        sincosf(ang, &sn, &cs);
                        float rx = cs * vx - sn * vy;
                        float ry = sn * vx + cs * vy;
                        if (part == 0) { rx *= 0.125f; ry *= 0.125f; dst = g_Q; }
                        else           { dst = g_K; }
                        o2 = make_float2(rx, ry);
                    }
                    size_t idx = (((size_t)b * NHEADS + h) * SLEN + s) * DHEAD + d;
                    *(float2*)(dst + idx) = o2;
                } else {
                    *(float2*)(C + (size_t)m * N + n) = make_float2(vx, vy);
                }
            }
        }
    }
}

// ---------------------------------------------------------------------------
// Flash attention (causal): BM=BN=64, d=64, 256 threads, 4x4 microtile.
// (unchanged from the passing round-3 kernel)
// ---------------------------------------------------------------------------
constexpr int AT_STR  = 68;                       // smem row stride (pad)
constexpr int AT_SMEM = 4 * 64 * AT_STR * 4;      // Qt + Kt + Vs + Ps = 69632 B

__global__ __launch_bounds__(256)
void flash_attn()
{
    extern __shared__ __align__(16) float sm[];
    float* Qt = sm;                    // [d][row]  (Q^T), stride AT_STR
    float* Kt = sm + 1 * 64 * AT_STR;  // [d][col]  (K^T)
    float* Vs = sm + 2 * 64 * AT_STR;  // [j][dd]
    float* Ps = sm + 3 * 64 * AT_STR;  // [j][row]  (P^T)

    const int tid = threadIdx.x;
    const int tx = tid & 15, ty = tid >> 4;
    const int bh = blockIdx.y;
    const int qt = gridDim.x - 1 - blockIdx.x;   // reversed scheduling
    const int i0 = qt * 64;

    int rowKV[4], d4KV[4];
#pragma unroll
    for (int ld = 0; ld < 4; ld++) {
        int id = tid + ld * 256;     // 0..1023
        rowKV[ld] = id >> 4;         // 0..63
        d4KV[ld]  = (id & 15) << 2;  // 0,4,...,60
    }

    const float* Qg = g_Q + ((size_t)bh * SLEN + i0) * DHEAD;
#pragma unroll
    for (int ld = 0; ld < 4; ld++) {
        float4 q = *(const float4*)(Qg + rowKV[ld] * DHEAD + d4KV[ld]);
        Qt[(d4KV[ld] + 0) * AT_STR + rowKV[ld]] = q.x;
        Qt[(d4KV[ld] + 1) * AT_STR + rowKV[ld]] = q.y;
        Qt[(d4KV[ld] + 2) * AT_STR + rowKV[ld]] = q.z;
        Qt[(d4KV[ld] + 3) * AT_STR + rowKV[ld]] = q.w;
    }

    const float* Kg0 = g_K + (size_t)bh * SLEN * DHEAD;
    const float* Vg0 = g_V + (size_t)bh * SLEN * DHEAD;
    float4 pk[4], pv[4];
#pragma unroll
    for (int ld = 0; ld < 4; ld++) {
        pk[ld] = *(const float4*)(Kg0 + rowKV[ld] * DHEAD + d4KV[ld]);
        pv[ld] = *(const float4*)(Vg0 + rowKV[ld] * DHEAD + d4KV[ld]);
    }

    float m_i[4], l_i[4], o[4][4];
#pragma unroll
    for (int i = 0; i < 4; i++) {
        m_i[i] = -3.0e38f;
        l_i[i] = 0.f;
#pragma unroll
        for (int c = 0; c < 4; c++) o[i][c] = 0.f;
    }

    for (int t = 0; t <= qt; t++) {
        __syncthreads();
#pragma unroll
        for (int ld = 0; ld < 4; ld++) {
            Kt[(d4KV[ld] + 0) * AT_STR + rowKV[ld]] = pk[ld].x;
            Kt[(d4KV[ld] + 1) * AT_STR + rowKV[ld]] = pk[ld].y;
            Kt[(d4KV[ld] + 2) * AT_STR + rowKV[ld]] = pk[ld].z;
            Kt[(d4KV[ld] + 3) * AT_STR + rowKV[ld]] = pk[ld].w;
            *(float4*)(Vs + rowKV[ld] * AT_STR + d4KV[ld]) = pv[ld];
        }
        __syncthreads();

        if (t + 1 <= qt) {
            const float* Kg = Kg0 + (size_t)(t + 1) * 64 * DHEAD;
            const float* Vg = Vg0 + (size_t)(t + 1) * 64 * DHEAD;
#pragma unroll
            for (int ld = 0; ld < 4; ld++) {
                pk[ld] = *(const float4*)(Kg + rowKV[ld] * DHEAD + d4KV[ld]);
                pv[ld] = *(const float4*)(Vg + rowKV[ld] * DHEAD + d4KV[ld]);
            }
        }

        float sc[4][4];
#pragma unroll
        for (int i = 0; i < 4; i++)
#pragma unroll
            for (int c = 0; c < 4; c++) sc[i][c] = 0.f;

#pragma unroll 8
        for (int d = 0; d < 64; d++) {
            float4 q = *(const float4*)(Qt + d * AT_STR + ty * 4);
            float4 k = *(const float4*)(Kt + d * AT_STR + tx * 4);
            float ra[4] = {q.x, q.y, q.z, q.w};
            float rb[4] = {k.x, k.y, k.z, k.w};
#pragma unroll
            for (int i = 0; i < 4; i++)
#pragma unroll
                for (int c = 0; c < 4; c++)
                    sc[i][c] = fmaf(ra[i], rb[c], sc[i][c]);
        }

        if (t == qt) {
#pragma unroll
            for (int i = 0; i < 4; i++)
#pragma unroll
                for (int c = 0; c < 4; c++)
                    if (tx * 4 + c > ty * 4 + i) sc[i][c] = -1.0e30f;
        }

#pragma unroll
        for (int i = 0; i < 4; i++) {
            float mx = fmaxf(fmaxf(sc[i][0], sc[i][1]), fmaxf(sc[i][2], sc[i][3]));
#pragma unroll
            for (int off = 8; off > 0; off >>= 1)
                mx = fmaxf(mx, __shfl_xor_sync(0xffffffffu, mx, off, 16));
            float mn = fmaxf(m_i[i], mx);
            float f  = __expf(m_i[i] - mn);
            m_i[i] = mn;
            float rs = 0.f;
#pragma unroll
            for (int c = 0; c < 4; c++) {
                sc[i][c] = __expf(sc[i][c] - mn);
                rs += sc[i][c];
            }
#pragma unroll
            for (int off = 8; off > 0; off >>= 1)
                rs += __shfl_xor_sync(0xffffffffu, rs, off, 16);
            l_i[i] = l_i[i] * f + rs;
#pragma unroll
            for (int c = 0; c < 4; c++) {
                o[i][c] *= f;
                Ps[(tx * 4 + c) * AT_STR + ty * 4 + i] = sc[i][c];
            }
        }
        __syncthreads();

#pragma unroll 8
        for (int j = 0; j < 64; j++) {
            float4 p  = *(const float4*)(Ps + j * AT_STR + ty * 4);
            float4 vv = *(const float4*)(Vs + j * AT_STR + tx * 4);
            float pa[4] = {p.x, p.y, p.z, p.w};
            float vb[4] = {vv.x, vv.y, vv.z, vv.w};
#pragma unroll
            for (int i = 0; i < 4; i++)
#pragma unroll
                for (int c = 0; c < 4; c++)
                    o[i][c] = fmaf(pa[i], vb[c], o[i][c]);
        }
    }

    const int b = bh >> 4, h = bh & 15;
#pragma unroll
    for (int i = 0; i < 4; i++) {
        float inv  = 1.f / l_i[i];
        int   srow = i0 + ty * 4 + i;
        float4 v = make_float4(o[i][0] * inv, o[i][1] * inv,
                               o[i][2] * inv, o[i][3] * inv);
        *(float4*)(g_AO + ((size_t)(b * SLEN + srow)) * DMODEL + h * DHEAD + tx * 4) = v;
    }
}

// ---------------------------------------------------------------------------
// Launch: inputs per metadata order: x, W_QKV, W_O, token_positions
// ---------------------------------------------------------------------------
extern "C" void kernel_launch(void* const* d_in, const int* in_sizes, int n_in,
                              void* d_out, int out_size)
{
    const float* x    = (const float*)d_in[0];   // [4,2048,1024]
    const float* wqkv = (const float*)d_in[1];   // [3072,1024]
    const float* wo   = (const float*)d_in[2];   // [1024,1024]
    const int*   tpos = (const int*)d_in[3];     // [2048] int32
    float* out = (float*)d_out;                  // [4,2048,1024]

    cudaFuncSetAttribute(flash_attn,  cudaFuncAttributeMaxDynamicSharedMemorySize, AT_SMEM);
    cudaFuncSetAttribute(sgemm_nt<1>, cudaFuncAttributeMaxDynamicSharedMemorySize, GEMM_SMEM);
    cudaFuncSetAttribute(sgemm_nt<2>, cudaFuncAttributeMaxDynamicSharedMemorySize, GEMM_SMEM);

    dim3 blk(256);
    // 1) QKV projection + RoPE + scatter (TF32 tensor cores)
    sgemm_nt<1><<<dim3(3 * DMODEL / BN, MROWS / BM), blk, GEMM_SMEM>>>(
        x, wqkv, nullptr, tpos, MROWS, 3 * DMODEL, DMODEL);
    // 2) causal flash attention (fp32)
    flash_attn<<<dim3(SLEN / 64, BATCH * NHEADS), blk, AT_SMEM>>>();
    // 3) output projection (TF32 tensor cores)
    sgemm_nt<2><<<dim3(DMODEL / BN, MROWS / BM), blk, GEMM_SMEM>>>(
        nullptr, wo, out, nullptr, MROWS, DMODEL, DMODEL);
}

// round 13
// speedup vs baseline: 2.4660x; 1.6715x over previous
#include <cuda_runtime.h>
#include <cstdint>

// Problem constants (fixed shapes from reference)
#define BATCH   4
#define SLEN    2048
#define DMODEL  1024
#define NHEADS  16
#define DHEAD   64
#define MROWS   (BATCH * SLEN)   // 8192

// Scratch (allocation-free rule: __device__ globals)
__device__ float g_Q[(size_t)BATCH * NHEADS * SLEN * DHEAD];   // [b,h,s,d], tf32-valued, pre-scaled 1/8
__device__ float g_K[(size_t)BATCH * NHEADS * SLEN * DHEAD];   // [b,h,s,d], tf32-valued
__device__ float g_V[(size_t)BATCH * NHEADS * SLEN * DHEAD];   // [b,h,s,d], tf32-valued
__device__ float g_AO[(size_t)MROWS * DMODEL];                 // attention output [b,s, h*d]

// ---------------------------------------------------------------------------
// TF32 tensor-core helpers
// ---------------------------------------------------------------------------
__device__ __forceinline__ float to_tf32(float x) {
    uint32_t r;
    asm("cvt.rna.tf32.f32 %0, %1;" : "=r"(r) : "f"(x));
    return __uint_as_float(r);
}

__device__ __forceinline__ void mma_tf32(float* d, const uint32_t* a, const uint32_t* b) {
    asm volatile(
        "mma.sync.aligned.m16n8k8.row.col.f32.tf32.tf32.f32 "
        "{%0,%1,%2,%3},{%4,%5,%6,%7},{%8,%9},{%0,%1,%2,%3};"
        : "+f"(d[0]), "+f"(d[1]), "+f"(d[2]), "+f"(d[3])
        : "r"(a[0]), "r"(a[1]), "r"(a[2]), "r"(a[3]), "r"(b[0]), "r"(b[1]));
}

__device__ __forceinline__ void cp16(uint32_t dst, const void* src) {
    asm volatile("cp.async.cg.shared.global [%0], [%1], 16;" :: "r"(dst), "l"(src));
}
__device__ __forceinline__ void cp_commit() {
    asm volatile("cp.async.commit_group;");
}
template <int N>
__device__ __forceinline__ void cp_wait() {
    asm volatile("cp.async.wait_group %0;" :: "n"(N));
}

// ---------------------------------------------------------------------------
// TF32 GEMM (NT): C[M,N] = A[M,K] * B[N,K]^T  (both operands K-contiguous)
// 128x128 block tile, BK=16, 256 threads (8 warps, 2x4 warp grid, warp tile
// 64x32). Double-buffered smem; inputs converted to tf32 at the smem store.
// MODE 1: QKV epilogue — RoPE on Q/K, fold 1/sqrt(dk) into Q, tf32-round,
//         scatter to g_Q/g_K/g_V in [b,h,s,d] layout
// MODE 2: A operand comes from g_AO (device scratch), plain store to C
// ---------------------------------------------------------------------------
constexpr int BM = 128, BN = 128, BK = 16;
constexpr int LDS_A = BM + 4;
constexpr int GEMM_SMEM = 2 * 2 * BK * LDS_A * 4;     // 67584 B

template <int MODE>
__global__ __launch_bounds__(256)
void sgemm_nt(const float* __restrict__ A, const float* __restrict__ Bw,
              float* __restrict__ C, const int* __restrict__ tpos,
              int M, int N, int K)
{
    extern __shared__ __align__(16) float sm[];
    float* Asm = sm;                       // As[2][BK][LDS_A] (k-major)
    float* Bsm = sm + 2 * BK * LDS_A;      // Bs[2][BK][LDS_A] (k-major)

    const float* Ap = (MODE == 2) ? (const float*)g_AO : A;

    const int tid  = threadIdx.x;
    const int wid  = tid >> 5;
    const int lane = tid & 31;
    const int gid  = lane >> 2;            // 0..7
    const int tig  = lane & 3;             // 0..3
    const int wm   = wid & 1;              // 2 warp rows of 64
    const int wn   = wid >> 1;             // 4 warp cols of 32
    const int mBase = blockIdx.y * BM;
    const int nBase = blockIdx.x * BN;

    int rowL[2], cvL[2];
#pragma unroll
    for (int ld = 0; ld < 2; ld++) {
        int id = tid + ld * 256;
        rowL[ld] = id >> 2;
        cvL[ld]  = (id & 3) << 2;
    }

    float acc[4][4][4];
#pragma unroll
    for (int i = 0; i < 4; i++)
#pragma unroll
        for (int j = 0; j < 4; j++)
#pragma unroll
            for (int r = 0; r < 4; r++) acc[i][j][r] = 0.f;

    float4 pa[2], pb[2];
#pragma unroll
    for (int ld = 0; ld < 2; ld++) {
        pa[ld] = *(const float4*)(Ap + (size_t)(mBase + rowL[ld]) * K + cvL[ld]);
        pb[ld] = *(const float4*)(Bw + (size_t)(nBase + rowL[ld]) * K + cvL[ld]);
    }
#pragma unroll
    for (int ld = 0; ld < 2; ld++) {
        Asm[(cvL[ld] + 0) * LDS_A + rowL[ld]] = to_tf32(pa[ld].x);
        Asm[(cvL[ld] + 1) * LDS_A + rowL[ld]] = to_tf32(pa[ld].y);
        Asm[(cvL[ld] + 2) * LDS_A + rowL[ld]] = to_tf32(pa[ld].z);
        Asm[(cvL[ld] + 3) * LDS_A + rowL[ld]] = to_tf32(pa[ld].w);
        Bsm[(cvL[ld] + 0) * LDS_A + rowL[ld]] = to_tf32(pb[ld].x);
        Bsm[(cvL[ld] + 1) * LDS_A + rowL[ld]] = to_tf32(pb[ld].y);
        Bsm[(cvL[ld] + 2) * LDS_A + rowL[ld]] = to_tf32(pb[ld].z);
        Bsm[(cvL[ld] + 3) * LDS_A + rowL[ld]] = to_tf32(pb[ld].w);
    }
    __syncthreads();

    const int mw = wm * 64 + gid;
    const int nw = wn * 32 + gid;

    const int nT = K / BK;
    for (int t = 0; t < nT; t++) {
        if (t + 1 < nT) {
            int k0 = (t + 1) * BK;
#pragma unroll
            for (int ld = 0; ld < 2; ld++) {
                pa[ld] = *(const float4*)(Ap + (size_t)(mBase + rowL[ld]) * K + k0 + cvL[ld]);
                pb[ld] = *(const float4*)(Bw + (size_t)(nBase + rowL[ld]) * K + k0 + cvL[ld]);
            }
        }

        const float* a = Asm + (t & 1) * BK * LDS_A;
        const float* b = Bsm + (t & 1) * BK * LDS_A;
#pragma unroll
        for (int ks = 0; ks < BK; ks += 8) {
            uint32_t af[4][4], bf[4][2];
#pragma unroll
            for (int i = 0; i < 4; i++) {
                int m = mw + i * 16;
                af[i][0] = __float_as_uint(a[(ks + tig)     * LDS_A + m]);
                af[i][1] = __float_as_uint(a[(ks + tig)     * LDS_A + m + 8]);
                af[i][2] = __float_as_uint(a[(ks + tig + 4) * LDS_A + m]);
                af[i][3] = __float_as_uint(a[(ks + tig + 4) * LDS_A + m + 8]);
            }
#pragma unroll
            for (int j = 0; j < 4; j++) {
                int n = nw + j * 8;
                bf[j][0] = __float_as_uint(b[(ks + tig)     * LDS_A + n]);
                bf[j][1] = __float_as_uint(b[(ks + tig + 4) * LDS_A + n]);
            }
#pragma unroll
            for (int i = 0; i < 4; i++)
#pragma unroll
                for (int j = 0; j < 4; j++)
                    mma_tf32(acc[i][j], af[i], bf[j]);
        }

        if (t + 1 < nT) {
            float* an = Asm + ((t + 1) & 1) * BK * LDS_A;
            float* bn = Bsm + ((t + 1) & 1) * BK * LDS_A;
#pragma unroll
            for (int ld = 0; ld < 2; ld++) {
                an[(cvL[ld] + 0) * LDS_A + rowL[ld]] = to_tf32(pa[ld].x);
                an[(cvL[ld] + 1) * LDS_A + rowL[ld]] = to_tf32(pa[ld].y);
                an[(cvL[ld] + 2) * LDS_A + rowL[ld]] = to_tf32(pa[ld].z);
                an[(cvL[ld] + 3) * LDS_A + rowL[ld]] = to_tf32(pa[ld].w);
                bn[(cvL[ld] + 0) * LDS_A + rowL[ld]] = to_tf32(pb[ld].x);
                bn[(cvL[ld] + 1) * LDS_A + rowL[ld]] = to_tf32(pb[ld].y);
                bn[(cvL[ld] + 2) * LDS_A + rowL[ld]] = to_tf32(pb[ld].z);
                bn[(cvL[ld] + 3) * LDS_A + rowL[ld]] = to_tf32(pb[ld].w);
            }
            __syncthreads();
        }
    }

    // Epilogue: thread owns float2 at row m = mBase+wm*64+i*16+gid+rr*8,
    // col n = nBase+wn*32+j*8+tig*2 (even -> valid RoPE pair)
#pragma unroll
    for (int i = 0; i < 4; i++) {
#pragma unroll
        for (int rr = 0; rr < 2; rr++) {
            int m = mBase + wm * 64 + i * 16 + gid + rr * 8;
#pragma unroll
            for (int j = 0; j < 4; j++) {
                int n = nBase + wn * 32 + j * 8 + tig * 2;
                float vx = acc[i][j][rr * 2 + 0];
                float vy = acc[i][j][rr * 2 + 1];
                if (MODE == 1) {
                    int b    = m >> 11;          // m / SLEN
                    int s    = m & (SLEN - 1);
                    int part = n >> 10;          // 0:q 1:k 2:v
                    int rem  = n & 1023;
                    int h    = rem >> 6;
                    int d    = rem & 63;         // even
                    float* dst;
                    float2 o2;
                    if (part == 2) {
                        dst = g_V;
                        o2 = make_float2(to_tf32(vx), to_tf32(vy));
                    } else {
                        float pos = (float)tpos[s];
                        // theta^(-d/64) = exp2(-d * log2(10000)/64)
                        float ang = pos * exp2f((float)d * -0.20762050593f);
                        float sn, cs;
                        sincosf(ang, &sn, &cs);
                        float rx = cs * vx - sn * vy;
                        float ry = sn * vx + cs * vy;
                        if (part == 0) { rx *= 0.125f; ry *= 0.125f; dst = g_Q; }
                        else           { dst = g_K; }
                        o2 = make_float2(to_tf32(rx), to_tf32(ry));
                    }
                    size_t idx = (((size_t)b * NHEADS + h) * SLEN + s) * DHEAD + d;
                    *(float2*)(dst + idx) = o2;
                } else {
                    *(float2*)(C + (size_t)m * N + n) = make_float2(vx, vy);
                }
            }
        }
    }
}

// ---------------------------------------------------------------------------
// TF32 flash attention (causal): BM=128 q rows, BN=64 kv, d=64, 256 threads.
// 8 warps; warp w owns q rows [w*16, w*16+16) -> softmax reductions are
// intra-quad shuffles. Q/K/V row-major [seq][d] stride 68 in smem (no
// transposes; conflict-free fragment loads). K/V double-buffered via cp.async.
// ---------------------------------------------------------------------------
constexpr int FSTR    = 68;
constexpr int FQ_OFF  = 0;                       // Qs [128][68]
constexpr int FK_OFF  = 128 * FSTR;              // Ks [2][64][68]
constexpr int FV_OFF  = FK_OFF + 2 * 64 * FSTR;  // Vs [2][64][68]
constexpr int FP_OFF  = FV_OFF + 2 * 64 * FSTR;  // Ps [128][68]
constexpr int FA_SMEM = (FP_OFF + 128 * FSTR) * 4;   // 139264 B

__global__ __launch_bounds__(256)
void flash_attn()
{
    extern __shared__ __align__(16) float sm[];
    float* Qs = sm + FQ_OFF;
    float* Ps = sm + FP_OFF;

    const int tid  = threadIdx.x;
    const int wid  = tid >> 5;
    const int lane = tid & 31;
    const int gid  = lane >> 2;            // 0..7
    const int tig  = lane & 3;             // 0..3
    const int bh   = blockIdx.y;
    const int qi   = gridDim.x - 1 - blockIdx.x;   // heavy CTAs first
    const int i0   = qi * 128;

    const float* Qg = g_Q + ((size_t)bh * SLEN + i0) * DHEAD;
    const float* Kg = g_K + (size_t)bh * SLEN * DHEAD;
    const float* Vg = g_V + (size_t)bh * SLEN * DHEAD;

    // Load Q tile: 128 rows x 64 -> 8 float4 per thread, row-major stride 68
#pragma unroll
    for (int l = 0; l < 8; l++) {
        int idx = tid + l * 256;         // 0..2047
        int row = idx >> 4;              // 0..127
        int c4  = (idx & 15) << 2;
        *(float4*)(Qs + row * FSTR + c4) = *(const float4*)(Qg + row * DHEAD + c4);
    }

    const uint32_t sKb = (uint32_t)__cvta_generic_to_shared(sm + FK_OFF);
    const uint32_t sVb = (uint32_t)__cvta_generic_to_shared(sm + FV_OFF);

    const int nT = 2 * qi + 2;           // kv tiles (64 each) to process

    // cp.async copy of tile t into buffer (t&1): 4 float4 K + 4 float4 V per thread
    auto issue_tile = [&](int t) {
        int buf = (t & 1) * 64 * FSTR;
        const float* ks = Kg + (size_t)t * 64 * DHEAD;
        const float* vs = Vg + (size_t)t * 64 * DHEAD;
#pragma unroll
        for (int l = 0; l < 4; l++) {
            int idx = tid + l * 256;     // 0..1023
            int row = idx >> 4;          // 0..63
            int c4  = (idx & 15) << 2;
            cp16(sKb + (buf + row * FSTR + c4) * 4, ks + row * DHEAD + c4);
            cp16(sVb + (buf + row * FSTR + c4) * 4, vs + row * DHEAD + c4);
        }
        cp_commit();
    };

    issue_tile(0);

    const int qr0 = wid * 16 + gid;      // this thread's row (and +8) in tile

    float m_i[2], l_i[2], acc_o[8][4];
#pragma unroll
    for (int r = 0; r < 2; r++) { m_i[r] = -3.0e38f; l_i[r] = 0.f; }
#pragma unroll
    for (int n = 0; n < 8; n++)
#pragma unroll
        for (int c = 0; c < 4; c++) acc_o[n][c] = 0.f;

    for (int t = 0; t < nT; t++) {
        if (t + 1 < nT) { issue_tile(t + 1); cp_wait<1>(); }
        else            { cp_wait<0>(); }
        __syncthreads();

        const float* K = sm + FK_OFF + (t & 1) * 64 * FSTR;
        const float* V = sm + FV_OFF + (t & 1) * 64 * FSTR;

        // S = Q K^T (Q pre-scaled by 1/8)
        float accs[8][4];
#pragma unroll
        for (int n = 0; n < 8; n++)
#pragma unroll
            for (int c = 0; c < 4; c++) accs[n][c] = 0.f;

#pragma unroll
        for (int ks = 0; ks < 64; ks += 8) {
            uint32_t af[4];
            af[0] = __float_as_uint(Qs[(qr0)     * FSTR + ks + tig]);
            af[1] = __float_as_uint(Qs[(qr0 + 8) * FSTR + ks + tig]);
            af[2] = __float_as_uint(Qs[(qr0)     * FSTR + ks + tig + 4]);
            af[3] = __float_as_uint(Qs[(qr0 + 8) * FSTR + ks + tig + 4]);
#pragma unroll
            for (int n = 0; n < 8; n++) {
                uint32_t bf[2];
                bf[0] = __float_as_uint(K[(n * 8 + gid) * FSTR + ks + tig]);
                bf[1] = __float_as_uint(K[(n * 8 + gid) * FSTR + ks + tig + 4]);
                mma_tf32(accs[n], af, bf);
            }
        }

        // Causal mask (only the last two kv tiles of this q block need it)
        if (t >= 2 * qi) {
            int qg0 = i0 + qr0;
            int qg1 = qg0 + 8;
#pragma unroll
            for (int n = 0; n < 8; n++) {
                int jb = t * 64 + n * 8 + tig * 2;
                if (jb     > qg0) accs[n][0] = -1.0e30f;
                if (jb + 1 > qg0) accs[n][1] = -1.0e30f;
                if (jb     > qg1) accs[n][2] = -1.0e30f;
                if (jb + 1 > qg1) accs[n][3] = -1.0e30f;
            }
        }

        // Online softmax; P (tf32) -> Ps
#pragma unroll
        for (int r = 0; r < 2; r++) {
            float mx = -3.0e38f;
#pragma unroll
            for (int n = 0; n < 8; n++)
                mx = fmaxf(mx, fmaxf(accs[n][2 * r], accs[n][2 * r + 1]));
            mx = fmaxf(mx, __shfl_xor_sync(0xffffffffu, mx, 1));
            mx = fmaxf(mx, __shfl_xor_sync(0xffffffffu, mx, 2));
            float mn = fmaxf(m_i[r], mx);
            float f  = __expf(m_i[r] - mn);
            m_i[r] = mn;
            float rs = 0.f;
#pragma unroll
            for (int n = 0; n < 8; n++) {
                float p0 = __expf(accs[n][2 * r]     - mn);
                float p1 = __expf(accs[n][2 * r + 1] - mn);
                rs += p0 + p1;
                *(float2*)(Ps + (qr0 + r * 8) * FSTR + n * 8 + tig * 2) =
                    make_float2(to_tf32(p0), to_tf32(p1));
            }
            rs += __shfl_xor_sync(0xffffffffu, rs, 1);
            rs += __shfl_xor_sync(0xffffffffu, rs, 2);
            l_i[r] = l_i[r] * f + rs;
#pragma unroll
            for (int n = 0; n < 8; n++) {
                acc_o[n][2 * r]     *= f;
                acc_o[n][2 * r + 1] *= f;
            }
        }
        __syncwarp();   // Ps is warp-private (16 own rows): warp-level visibility

        // O += P V
#pragma unroll
        for (int ks = 0; ks < 64; ks += 8) {
            uint32_t af[4];
            af[0] = __float_as_uint(Ps[(qr0)     * FSTR + ks + tig]);
            af[1] = __float_as_uint(Ps[(qr0 + 8) * FSTR + ks + tig]);
            af[2] = __float_as_uint(Ps[(qr0)     * FSTR + ks + tig + 4]);
            af[3] = __float_as_uint(Ps[(qr0 + 8) * FSTR + ks + tig + 4]);
#pragma unroll
            for (int n = 0; n < 8; n++) {
                uint32_t bf[2];
                bf[0] = __float_as_uint(V[(ks + tig)     * FSTR + n * 8 + gid]);
                bf[1] = __float_as_uint(V[(ks + tig + 4) * FSTR + n * 8 + gid]);
                mma_tf32(acc_o[n], af, bf);
            }
        }
        __syncthreads();   // K/V buffer reads done before next overwrite
    }

    // Normalize, write O to [b, s, h*64 + d] scratch
    const int b = bh >> 4, h = bh & 15;
#pragma unroll
    for (int r = 0; r < 2; r++) {
        float inv = 1.f / l_i[r];
        int srow  = i0 + qr0 + r * 8;
        float* dst = g_AO + ((size_t)(b * SLEN + srow)) * DMODEL + h * DHEAD;
#pragma unroll
        for (int n = 0; n < 8; n++)
            *(float2*)(dst + n * 8 + tig * 2) =
                make_float2(acc_o[n][2 * r] * inv, acc_o[n][2 * r + 1] * inv);
    }
}

// ---------------------------------------------------------------------------
// Launch: inputs per metadata order: x, W_QKV, W_O, token_positions
// ---------------------------------------------------------------------------
extern "C" void kernel_launch(void* const* d_in, const int* in_sizes, int n_in,
                              void* d_out, int out_size)
{
    const float* x    = (const float*)d_in[0];   // [4,2048,1024]
    const float* wqkv = (const float*)d_in[1];   // [3072,1024]
    const float* wo   = (const float*)d_in[2];   // [1024,1024]
    const int*   tpos = (const int*)d_in[3];     // [2048] int32
    float* out = (float*)d_out;                  // [4,2048,1024]

    cudaFuncSetAttribute(flash_attn,  cudaFuncAttributeMaxDynamicSharedMemorySize, FA_SMEM);
    cudaFuncSetAttribute(sgemm_nt<1>, cudaFuncAttributeMaxDynamicSharedMemorySize, GEMM_SMEM);
    cudaFuncSetAttribute(sgemm_nt<2>, cudaFuncAttributeMaxDynamicSharedMemorySize, GEMM_SMEM);

    dim3 blk(256);
    // 1) QKV projection + RoPE + scatter (TF32 tensor cores)
    sgemm_nt<1><<<dim3(3 * DMODEL / BN, MROWS / BM), blk, GEMM_SMEM>>>(
        x, wqkv, nullptr, tpos, MROWS, 3 * DMODEL, DMODEL);
    // 2) causal flash attention (TF32 tensor cores)
    flash_attn<<<dim3(SLEN / 128, BATCH * NHEADS), blk, FA_SMEM>>>();
    // 3) output projection (TF32 tensor cores)
    sgemm_nt<2><<<dim3(DMODEL / BN, MROWS / BM), blk, GEMM_SMEM>>>(
        nullptr, wo, out, nullptr, MROWS, DMODEL, DMODEL);
}